// round 1
// baseline (speedup 1.0000x reference)
#include <cuda_runtime.h>
#include <cuda_bf16.h>

// Downsampler: (16,8,1024,1024) fp32, 4x4 Gaussian kernel, stride 4, VALID.
// Output (16,8,256,256) fp32. Non-overlapping windows -> pure streaming:
// each input element read exactly once. HBM-bound: 544 MB total traffic.

#define N_  16
#define C_  8
#define H_  1024
#define W_  1024
#define F_  4
#define HO_ (H_ / F_)   // 256
#define WO_ (W_ / F_)   // 256

__global__ __launch_bounds__(256) void Downsampler_24421184045082_kernel(
    const float* __restrict__ x,
    const float* __restrict__ kern,
    float* __restrict__ out,
    int total)
{
    int o = blockIdx.x * blockDim.x + threadIdx.x;
    if (o >= total) return;

    // Decompose output index: o = ((nc * HO) + oh) * WO + ow
    int ow = o & (WO_ - 1);            // 256 = 2^8
    int oh = (o >> 8) & (HO_ - 1);
    int nc = o >> 16;

    // Load 4x4 weights into registers (uniform across warp; L1/const-cached).
    float k00 = __ldg(kern + 0),  k01 = __ldg(kern + 1),  k02 = __ldg(kern + 2),  k03 = __ldg(kern + 3);
    float k10 = __ldg(kern + 4),  k11 = __ldg(kern + 5),  k12 = __ldg(kern + 6),  k13 = __ldg(kern + 7);
    float k20 = __ldg(kern + 8),  k21 = __ldg(kern + 9),  k22 = __ldg(kern + 10), k23 = __ldg(kern + 11);
    float k30 = __ldg(kern + 12), k31 = __ldg(kern + 13), k32 = __ldg(kern + 14), k33 = __ldg(kern + 15);

    // Base of this thread's 4x4 patch, viewed as float4 rows.
    // Row r of the patch: x[nc, oh*4 + r, ow*4 .. ow*4+3] == one aligned float4.
    const float4* x4 = reinterpret_cast<const float4*>(x)
                     + (size_t)nc * (H_ * (W_ / 4))
                     + (size_t)(oh * F_) * (W_ / 4)
                     + ow;

    // Issue all 4 independent row loads up front (MLP=4), then reduce.
    float4 r0 = __ldg(x4 + 0 * (W_ / 4));
    float4 r1 = __ldg(x4 + 1 * (W_ / 4));
    float4 r2 = __ldg(x4 + 2 * (W_ / 4));
    float4 r3 = __ldg(x4 + 3 * (W_ / 4));

    float acc;
    acc  = k00 * r0.x + k01 * r0.y + k02 * r0.z + k03 * r0.w;
    acc += k10 * r1.x + k11 * r1.y + k12 * r1.z + k13 * r1.w;
    acc += k20 * r2.x + k21 * r2.y + k22 * r2.z + k23 * r2.w;
    acc += k30 * r3.x + k31 * r3.y + k32 * r3.z + k33 * r3.w;

    out[o] = acc;
}

extern "C" void kernel_launch(void* const* d_in, const int* in_sizes, int n_in,
                              void* d_out, int out_size)
{
    const float* x    = (const float*)d_in[0];   // (16,8,1024,1024) fp32
    const float* kern = (const float*)d_in[1];   // (4,4) fp32
    float* out = (float*)d_out;                  // (16,8,256,256) fp32

    int total = N_ * C_ * HO_ * WO_;             // 16,777,216
    int threads = 256;
    int blocks = (total + threads - 1) / threads; // 65536
    Downsampler_24421184045082_kernel<<<blocks, threads>>>(x, kern, out, total);
}